// round 3
// baseline (speedup 1.0000x reference)
#include <cuda_runtime.h>
#include <cuda_bf16.h>
#include <math.h>

#define BB   512   // batch
#define TT   128   // time steps
#define FF   256   // features
#define HH   512   // hidden
#define KK   3     // fuzzy rules

typedef unsigned long long ull;

// ------------------------------------------------------------------
// Device scratch
// ------------------------------------------------------------------
__device__ float g_xw[(size_t)TT * BB * HH];   // [T][B][H]
__device__ float g_h2[2][(size_t)BB * HH];     // ping-pong hidden state [B][H]
__device__ float g_Wxs[FF * HH];               // diag(sigmoid(theta)) @ Wx
__device__ float g_gp[(HH / 2) * 20];          // packed gate params per column-pair

// ------------------------------------------------------------------
// Packed f32x2 helpers
// ------------------------------------------------------------------
__device__ __forceinline__ ull pack2(float x, float y) {
    ull r; asm("mov.b64 %0, {%1, %2};" : "=l"(r) : "f"(x), "f"(y)); return r;
}
__device__ __forceinline__ float2 unpack2(ull v) {
    float2 r; asm("mov.b64 {%0, %1}, %2;" : "=f"(r.x), "=f"(r.y) : "l"(v)); return r;
}
__device__ __forceinline__ ull fma2(ull a, ull b, ull c) {
    ull d; asm("fma.rn.f32x2 %0, %1, %2, %3;" : "=l"(d) : "l"(a), "l"(b), "l"(c)); return d;
}

// ------------------------------------------------------------------
// Prep: zero h0, fold selector into Wx, emit weights, pack gate params.
// gp layout per column-pair np (cols 2np, 2np+1), 20 floats:
//  [0..2]=c0  [3]=b0  [4..6]=inv0  [7..9]=q0
//  [10..12]=c1 [13]=b1 [14..16]=inv1 [17..19]=q1
// ------------------------------------------------------------------
__global__ void prep_kernel(const float* __restrict__ theta,
                            const float* __restrict__ Wx,
                            const float* __restrict__ sigma,
                            const float* __restrict__ cC,
                            const float* __restrict__ qQ,
                            const float* __restrict__ bias,
                            float* __restrict__ out)
{
    int idx = blockIdx.x * blockDim.x + threadIdx.x;
    if (idx < BB * HH) g_h2[0][idx] = 0.0f;
    if (idx < FF * HH) {
        int f = idx >> 9;
        float w = 1.0f / (1.0f + expf(-theta[f]));
        g_Wxs[idx] = w * Wx[idx];
    }
    if (idx < FF) out[BB + idx] = 1.0f / (1.0f + expf(-theta[idx]));
    if (idx < HH / 2) {
        float* gp = g_gp + idx * 20;
        #pragma unroll
        for (int j = 0; j < 2; ++j) {
            int col = idx * 2 + j;
            float* o = gp + j * 10;
            #pragma unroll
            for (int s = 0; s < 3; ++s) {
                float sg = sigma[col * 3 + s];
                o[0 + s] = cC[col * 3 + s];
                o[4 + s] = 1.0f / (2.0f * sg * sg + 1e-8f);
                o[7 + s] = qQ[col * 3 + s];
            }
            o[3] = bias[col];
        }
    }
}

// ------------------------------------------------------------------
// GEMM1: g_xw[t][b][h] = sum_f x[b][t][f] * Wxs[f][h]   (unchanged, proven)
// ------------------------------------------------------------------
__global__ void __launch_bounds__(256) gemm1_kernel(const float* __restrict__ x)
{
    __shared__ float sA[16][130];
    __shared__ float sB[16][128];

    const int tid = threadIdx.x;
    const int m0  = blockIdx.x * 128;
    const int n0  = blockIdx.y * 128;

    const int ar = tid >> 1;
    const int ak = (tid & 1) * 8;
    const int bk = tid >> 4;
    const int bc = (tid & 15) * 8;

    const float* Ag = x     + (size_t)(m0 + ar) * FF + ak;
    const float* Bg = g_Wxs + (size_t)bk * HH + n0 + bc;

    float4 ra0 = *(const float4*)(Ag);
    float4 ra1 = *(const float4*)(Ag + 4);
    float4 rb0 = *(const float4*)(Bg);
    float4 rb1 = *(const float4*)(Bg + 4);

    ull acc[4][8];
    #pragma unroll
    for (int i = 0; i < 4; ++i)
        #pragma unroll
        for (int j = 0; j < 8; ++j) acc[i][j] = 0ull;

    const int ty = tid >> 4;
    const int tx = tid & 15;

    #pragma unroll 1
    for (int kt = 0; kt < FF / 16; ++kt) {
        sA[ak + 0][ar] = ra0.x; sA[ak + 1][ar] = ra0.y;
        sA[ak + 2][ar] = ra0.z; sA[ak + 3][ar] = ra0.w;
        sA[ak + 4][ar] = ra1.x; sA[ak + 5][ar] = ra1.y;
        sA[ak + 6][ar] = ra1.z; sA[ak + 7][ar] = ra1.w;
        *(float4*)&sB[bk][bc]     = rb0;
        *(float4*)&sB[bk][bc + 4] = rb1;
        __syncthreads();

        if (kt < FF / 16 - 1) {
            const float* Ag2 = Ag + (kt + 1) * 16;
            const float* Bg2 = Bg + (size_t)(kt + 1) * 16 * HH;
            ra0 = *(const float4*)(Ag2);
            ra1 = *(const float4*)(Ag2 + 4);
            rb0 = *(const float4*)(Bg2);
            rb1 = *(const float4*)(Bg2 + 4);
        }

        #pragma unroll
        for (int kk = 0; kk < 16; ++kk) {
            ull a2[4];
            #pragma unroll
            for (int i = 0; i < 4; ++i)
                a2[i] = *(const ull*)&sA[kk][ty * 8 + 2 * i];
            float bf[8];
            *(float4*)&bf[0] = *(const float4*)&sB[kk][tx * 8];
            *(float4*)&bf[4] = *(const float4*)&sB[kk][tx * 8 + 4];
            #pragma unroll
            for (int j = 0; j < 8; ++j) {
                ull bbv = pack2(bf[j], bf[j]);
                #pragma unroll
                for (int i = 0; i < 4; ++i)
                    acc[i][j] = fma2(a2[i], bbv, acc[i][j]);
            }
        }
        __syncthreads();
    }

    #pragma unroll
    for (int i = 0; i < 4; ++i) {
        float2 v[8];
        #pragma unroll
        for (int j = 0; j < 8; ++j) v[j] = unpack2(acc[i][j]);
        #pragma unroll
        for (int p = 0; p < 2; ++p) {
            int m = m0 + ty * 8 + 2 * i + p;
            int t = m & (TT - 1);
            int b = m >> 7;
            float* orow = g_xw + ((size_t)t * BB + b) * HH + n0 + tx * 8;
            float4 o0, o1;
            if (p == 0) {
                o0 = make_float4(v[0].x, v[1].x, v[2].x, v[3].x);
                o1 = make_float4(v[4].x, v[5].x, v[6].x, v[7].x);
            } else {
                o0 = make_float4(v[0].y, v[1].y, v[2].y, v[3].y);
                o1 = make_float4(v[4].y, v[5].y, v[6].y, v[7].y);
            }
            *(float4*)(orow)     = o0;
            *(float4*)(orow + 4) = o1;
        }
    }
}

// ------------------------------------------------------------------
// Step kernel: one per t. CTA tile 64(batch) x 32(hidden), grid 8x16.
// A (=h) staged k-major/m-minor so LDS.128 gives m-pair ulls directly.
// B (=Wh) staged PRE-DUPLICATED so LDS.128 gives {b,b,b',b'} directly.
// Inner loop: 2 LDS.128 + 4 FFMA2 per k. Zero pack instructions.
// ------------------------------------------------------------------
__global__ void __launch_bounds__(256) step_kernel(const float* __restrict__ Wh,
                                                   int t)
{
    __shared__ float sA[16 * 64];    // [k][m]     4 KB
    __shared__ float sBd[16 * 64];   // [k][2n dup] 4 KB

    const int tid = threadIdx.x;
    const int m0  = blockIdx.x * 64;   // grid.x = 8
    const int n0  = blockIdx.y * 32;   // grid.y = 16

    const float* hcur = g_h2[t & 1];
    float*       hnxt = g_h2[(t + 1) & 1];

    // microtile mapping: 8 warps = 2(m) x 4(n); warp tile 32m x 8n; thread 4m x 2n
    const int warp = tid >> 5;
    const int lane = tid & 31;
    const int wm   = warp & 1;
    const int wn   = warp >> 1;
    const int mg   = lane & 7;
    const int ng   = lane >> 3;
    const int mloc = wm * 32 + mg * 4;       // local row base (4 rows)
    const int nloc = wn * 8 + ng * 2;        // local col base (2 cols)

    // staging indices
    const int am = tid >> 2;            // 0..63  (batch row)
    const int akq = tid & 3;            // 0..3   (k quad)
    const int bk = tid >> 4;            // 0..15  (k row)
    const int bnp = tid & 15;           // 0..15  (n pair)

    const float* Ag = hcur + (size_t)(m0 + am) * HH + akq * 4;
    const float* Bg = Wh   + (size_t)bk * HH + n0 + bnp * 2;

    float4 ra = *(const float4*)(Ag);
    float2 rb = *(const float2*)(Bg);

    ull acc00 = 0, acc01 = 0, acc10 = 0, acc11 = 0;

    #pragma unroll 1
    for (int kt = 0; kt < HH / 16; ++kt) {
        // store staged chunk
        sA[(akq * 4 + 0) * 64 + am] = ra.x;
        sA[(akq * 4 + 1) * 64 + am] = ra.y;
        sA[(akq * 4 + 2) * 64 + am] = ra.z;
        sA[(akq * 4 + 3) * 64 + am] = ra.w;
        *(float4*)&sBd[bk * 64 + bnp * 4] = make_float4(rb.x, rb.x, rb.y, rb.y);
        __syncthreads();

        if (kt < HH / 16 - 1) {
            ra = *(const float4*)(Ag + (kt + 1) * 16);
            rb = *(const float2*)(Bg + (size_t)(kt + 1) * 16 * HH);
        }

        #pragma unroll
        for (int k = 0; k < 16; ++k) {
            ulonglong2 av = *(const ulonglong2*)&sA[k * 64 + mloc];
            ulonglong2 bv = *(const ulonglong2*)&sBd[k * 64 + nloc * 2];
            acc00 = fma2(av.x, bv.x, acc00);
            acc01 = fma2(av.x, bv.y, acc01);
            acc10 = fma2(av.y, bv.x, acc10);
            acc11 = fma2(av.y, bv.y, acc11);
        }
        __syncthreads();
    }

    // ---- fused gate epilogue ----
    // z rows: r0..r0+3 ; cols: col, col+1
    const int r0  = m0 + mloc;
    const int col = n0 + nloc;
    const float* xwt = g_xw + (size_t)t * (BB * HH);

    // gate params for this column pair
    const float* gp = g_gp + (size_t)(col >> 1) * 20;
    float4 p0 = *(const float4*)(gp + 0);    // c0.xyz, b0
    float4 p1 = *(const float4*)(gp + 4);    // i0.xyz, q0_0
    float4 p2 = *(const float4*)(gp + 8);    // wait: gp+8 = q0_1,q0_2,c1_0,c1_1
    float4 p3 = *(const float4*)(gp + 12);   // c1_2, b1, i1_0, i1_1
    float4 p4 = *(const float4*)(gp + 16);   // i1_2, q1_0, q1_1, q1_2

    float cc[2][3]  = {{p0.x, p0.y, p0.z}, {p2.z, p2.w, p3.x}};
    float bb2[2]    = {p0.w, p3.y};
    float iv[2][3]  = {{p1.x, p1.y, p1.z}, {p3.z, p3.w, p4.x}};
    float qq[2][3]  = {{p1.w, p2.x, p2.y}, {p4.y, p4.z, p4.w}};

    float zr[4][2];
    { float2 v = unpack2(acc00); zr[0][0] = v.x; zr[1][0] = v.y; }
    { float2 v = unpack2(acc01); zr[0][1] = v.x; zr[1][1] = v.y; }
    { float2 v = unpack2(acc10); zr[2][0] = v.x; zr[3][0] = v.y; }
    { float2 v = unpack2(acc11); zr[2][1] = v.x; zr[3][1] = v.y; }

    #pragma unroll
    for (int i = 0; i < 4; ++i) {
        const size_t off = (size_t)(r0 + i) * HH + col;
        float2 xv = *(const float2*)&xwt[off];
        float2 hv = *(const float2*)&hcur[off];
        float hn[2];
        #pragma unroll
        for (int j = 0; j < 2; ++j) {
            float x  = j ? xv.y : xv.x;
            float hi = j ? hv.y : hv.x;
            float z  = zr[i][j] + x + bb2[j];
            float d0 = z - cc[j][0], d1 = z - cc[j][1], d2 = z - cc[j][2];
            float mu0 = __expf(-d0 * d0 * iv[j][0]);
            float mu1 = __expf(-d1 * d1 * iv[j][1]);
            float mu2 = __expf(-d2 * d2 * iv[j][2]);
            float num = mu0 * qq[j][0] + mu1 * qq[j][1] + mu2 * qq[j][2];
            float den = mu0 + mu1 + mu2 + 1e-8f;
            float g   = 1.0f / (1.0f + __expf(-num / den));
            float ex  = __expf(-2.0f * x);
            float ni  = (1.0f - ex) / (1.0f + ex);
            hn[j] = (1.0f - g) * hi + g * ni;
        }
        *(float2*)&hnxt[off] = make_float2(hn[0], hn[1]);
    }
}

// ------------------------------------------------------------------
// Final: logits[b] = h_final[b] . Wc + bc ; one warp per batch row.
// ------------------------------------------------------------------
__global__ void __launch_bounds__(256) final_kernel(const float* __restrict__ Wc,
                                                    const float* __restrict__ bc,
                                                    float* __restrict__ out)
{
    const int warp = threadIdx.x >> 5;
    const int lane = threadIdx.x & 31;
    const int b = blockIdx.x * 8 + warp;       // 64 blocks x 8 warps = 512
    const float* hrow = g_h2[0] + (size_t)b * HH;
    float s = 0.0f;
    #pragma unroll
    for (int i = 0; i < 4; ++i) {
        float4 h4 = *(const float4*)&hrow[i * 128 + lane * 4];
        float4 w4 = *(const float4*)&Wc[i * 128 + lane * 4];
        s += h4.x * w4.x + h4.y * w4.y + h4.z * w4.z + h4.w * w4.w;
    }
    #pragma unroll
    for (int o = 16; o > 0; o >>= 1) s += __shfl_down_sync(0xffffffffu, s, o);
    if (lane == 0) out[b] = s + bc[0];
}

// ------------------------------------------------------------------
// Launch
// ------------------------------------------------------------------
extern "C" void kernel_launch(void* const* d_in, const int* in_sizes, int n_in,
                              void* d_out, int out_size)
{
    const float* x     = (const float*)d_in[0];
    const float* theta = (const float*)d_in[1];
    const float* Wx    = (const float*)d_in[2];
    const float* Wh    = (const float*)d_in[3];
    const float* bias  = (const float*)d_in[4];
    const float* c     = (const float*)d_in[5];
    const float* sigma = (const float*)d_in[6];
    const float* q     = (const float*)d_in[7];
    const float* Wc    = (const float*)d_in[8];
    const float* bc    = (const float*)d_in[9];
    float* out = (float*)d_out;

    prep_kernel<<<(BB * HH + 255) / 256, 256>>>(theta, Wx, sigma, c, q, bias, out);
    gemm1_kernel<<<dim3((BB * TT) / 128, HH / 128), 256>>>(x);
    for (int t = 0; t < TT; ++t)
        step_kernel<<<dim3(8, 16), 256>>>(Wh, t);
    final_kernel<<<64, 256>>>(Wc, bc, out);
}

// round 4
// speedup vs baseline: 1.0495x; 1.0495x over previous
#include <cuda_runtime.h>
#include <cuda_bf16.h>
#include <math.h>

#define BB   512   // batch
#define TT   128   // time steps
#define FF   256   // features
#define HH   512   // hidden
#define KK   3     // fuzzy rules

typedef unsigned long long ull;

// ------------------------------------------------------------------
// Device scratch
// ------------------------------------------------------------------
__device__ float g_xw[(size_t)TT * BB * HH];   // [T][B][H]
__device__ float g_h2[2][(size_t)BB * HH];     // ping-pong hidden state [B][H]
__device__ float g_Wxs[FF * HH];               // diag(sigmoid(theta)) @ Wx
__device__ float g_gp[(HH / 2) * 20];          // packed gate params per column-pair

// ------------------------------------------------------------------
// Packed f32x2 helpers
// ------------------------------------------------------------------
__device__ __forceinline__ ull pack2(float x, float y) {
    ull r; asm("mov.b64 %0, {%1, %2};" : "=l"(r) : "f"(x), "f"(y)); return r;
}
__device__ __forceinline__ float2 unpack2(ull v) {
    float2 r; asm("mov.b64 {%0, %1}, %2;" : "=f"(r.x), "=f"(r.y) : "l"(v)); return r;
}
__device__ __forceinline__ ull fma2(ull a, ull b, ull c) {
    ull d; asm("fma.rn.f32x2 %0, %1, %2, %3;" : "=l"(d) : "l"(a), "l"(b), "l"(c)); return d;
}

// ------------------------------------------------------------------
// Prep: zero h0, fold selector into Wx, emit weights, pack gate params.
// gp layout per column-pair (cols 2p, 2p+1), 20 floats:
//  [0..2]=c0 [3]=b0 [4..6]=inv0 [7..9]=q0 ; [10..12]=c1 [13]=b1 [14..16]=inv1 [17..19]=q1
// ------------------------------------------------------------------
__global__ void prep_kernel(const float* __restrict__ theta,
                            const float* __restrict__ Wx,
                            const float* __restrict__ sigma,
                            const float* __restrict__ cC,
                            const float* __restrict__ qQ,
                            const float* __restrict__ bias,
                            float* __restrict__ out)
{
    int idx = blockIdx.x * blockDim.x + threadIdx.x;
    if (idx < BB * HH) g_h2[0][idx] = 0.0f;
    if (idx < FF * HH) {
        int f = idx >> 9;
        float w = 1.0f / (1.0f + expf(-theta[f]));
        g_Wxs[idx] = w * Wx[idx];
    }
    if (idx < FF) out[BB + idx] = 1.0f / (1.0f + expf(-theta[idx]));
    if (idx < HH / 2) {
        float* gp = g_gp + idx * 20;
        #pragma unroll
        for (int j = 0; j < 2; ++j) {
            int col = idx * 2 + j;
            float* o = gp + j * 10;
            #pragma unroll
            for (int s = 0; s < 3; ++s) {
                float sg = sigma[col * 3 + s];
                o[0 + s] = cC[col * 3 + s];
                o[4 + s] = 1.0f / (2.0f * sg * sg + 1e-8f);
                o[7 + s] = qQ[col * 3 + s];
            }
            o[3] = bias[col];
        }
    }
}

// ------------------------------------------------------------------
// GEMM1 (proven): g_xw[t][b][h] = sum_f x[b][t][f] * Wxs[f][h]
// ------------------------------------------------------------------
__global__ void __launch_bounds__(256) gemm1_kernel(const float* __restrict__ x)
{
    __shared__ float sA[16][130];
    __shared__ float sB[16][128];

    const int tid = threadIdx.x;
    const int m0  = blockIdx.x * 128;
    const int n0  = blockIdx.y * 128;

    const int ar = tid >> 1;
    const int ak = (tid & 1) * 8;
    const int bk = tid >> 4;
    const int bc = (tid & 15) * 8;

    const float* Ag = x     + (size_t)(m0 + ar) * FF + ak;
    const float* Bg = g_Wxs + (size_t)bk * HH + n0 + bc;

    float4 ra0 = *(const float4*)(Ag);
    float4 ra1 = *(const float4*)(Ag + 4);
    float4 rb0 = *(const float4*)(Bg);
    float4 rb1 = *(const float4*)(Bg + 4);

    ull acc[4][8];
    #pragma unroll
    for (int i = 0; i < 4; ++i)
        #pragma unroll
        for (int j = 0; j < 8; ++j) acc[i][j] = 0ull;

    const int ty = tid >> 4;
    const int tx = tid & 15;

    #pragma unroll 1
    for (int kt = 0; kt < FF / 16; ++kt) {
        sA[ak + 0][ar] = ra0.x; sA[ak + 1][ar] = ra0.y;
        sA[ak + 2][ar] = ra0.z; sA[ak + 3][ar] = ra0.w;
        sA[ak + 4][ar] = ra1.x; sA[ak + 5][ar] = ra1.y;
        sA[ak + 6][ar] = ra1.z; sA[ak + 7][ar] = ra1.w;
        *(float4*)&sB[bk][bc]     = rb0;
        *(float4*)&sB[bk][bc + 4] = rb1;
        __syncthreads();

        if (kt < FF / 16 - 1) {
            const float* Ag2 = Ag + (kt + 1) * 16;
            const float* Bg2 = Bg + (size_t)(kt + 1) * 16 * HH;
            ra0 = *(const float4*)(Ag2);
            ra1 = *(const float4*)(Ag2 + 4);
            rb0 = *(const float4*)(Bg2);
            rb1 = *(const float4*)(Bg2 + 4);
        }

        #pragma unroll
        for (int kk = 0; kk < 16; ++kk) {
            ull a2[4];
            #pragma unroll
            for (int i = 0; i < 4; ++i)
                a2[i] = *(const ull*)&sA[kk][ty * 8 + 2 * i];
            float bf[8];
            *(float4*)&bf[0] = *(const float4*)&sB[kk][tx * 8];
            *(float4*)&bf[4] = *(const float4*)&sB[kk][tx * 8 + 4];
            #pragma unroll
            for (int j = 0; j < 8; ++j) {
                ull bbv = pack2(bf[j], bf[j]);
                #pragma unroll
                for (int i = 0; i < 4; ++i)
                    acc[i][j] = fma2(a2[i], bbv, acc[i][j]);
            }
        }
        __syncthreads();
    }

    #pragma unroll
    for (int i = 0; i < 4; ++i) {
        float2 v[8];
        #pragma unroll
        for (int j = 0; j < 8; ++j) v[j] = unpack2(acc[i][j]);
        #pragma unroll
        for (int p = 0; p < 2; ++p) {
            int m = m0 + ty * 8 + 2 * i + p;
            int t = m & (TT - 1);
            int b = m >> 7;
            float* orow = g_xw + ((size_t)t * BB + b) * HH + n0 + tx * 8;
            float4 o0, o1;
            if (p == 0) {
                o0 = make_float4(v[0].x, v[1].x, v[2].x, v[3].x);
                o1 = make_float4(v[4].x, v[5].x, v[6].x, v[7].x);
            } else {
                o0 = make_float4(v[0].y, v[1].y, v[2].y, v[3].y);
                o1 = make_float4(v[4].y, v[5].y, v[6].y, v[7].y);
            }
            *(float4*)(orow)     = o0;
            *(float4*)(orow + 4) = o1;
        }
    }
}

// ------------------------------------------------------------------
// Step kernel v3: 512 threads, K-split by 2, double-buffered smem.
// CTA tile 64(batch) x 32(hidden), grid 8x16 = 128 CTAs.
// BK=32 per chunk; warps 0-7 compute k[0:16) of chunk, warps 8-15 k[16:32).
// One __syncthreads per chunk. Partials reduced via smem at the end.
// ------------------------------------------------------------------
__global__ void __launch_bounds__(512, 1) step_kernel(const float* __restrict__ Wh,
                                                      int t)
{
    __shared__ float sA[2][32 * 64];    // [buf][k][m]       2 x 8 KB
    __shared__ float sBd[2][32 * 64];   // [buf][k][2n dup]  2 x 8 KB

    const int tid = threadIdx.x;
    const int m0  = blockIdx.x * 64;    // grid.x = 8
    const int n0  = blockIdx.y * 32;    // grid.y = 16

    const float* hcur = g_h2[t & 1];
    float*       hnxt = g_h2[(t + 1) & 1];

    const int warp = tid >> 5;
    const int lane = tid & 31;
    const int kg   = warp >> 3;         // K-split group 0/1
    const int wg   = warp & 7;          // warp-in-group
    const int wm   = wg & 1;
    const int wn   = wg >> 1;
    const int mg   = lane & 7;
    const int ng   = lane >> 3;
    const int mloc = wm * 32 + mg * 4;  // local row base (4 rows)
    const int nloc = wn * 8 + ng * 2;   // local col base (2 cols)
    const int kbase = kg * 16;

    // staging indices (all 512 threads)
    const int am  = tid & 63;           // batch row 0..63
    const int ak4 = (tid >> 6) << 2;    // k quad base 0,4,...,28
    const int bk  = tid >> 4;           // k row 0..31
    const int bnp = tid & 15;           // n pair 0..15

    const float* Ag = hcur + (size_t)(m0 + am) * HH + ak4;
    const float* Bg = Wh   + (size_t)bk * HH + n0 + bnp * 2;

    // ---- prologue: stage chunk 0 ----
    float4 ra = *(const float4*)(Ag);
    float2 rb = *(const float2*)(Bg);
    sA[0][(ak4 + 0) * 64 + am] = ra.x;
    sA[0][(ak4 + 1) * 64 + am] = ra.y;
    sA[0][(ak4 + 2) * 64 + am] = ra.z;
    sA[0][(ak4 + 3) * 64 + am] = ra.w;
    *(float4*)&sBd[0][bk * 64 + bnp * 4] = make_float4(rb.x, rb.x, rb.y, rb.y);
    __syncthreads();

    ull acc00 = 0, acc01 = 0, acc10 = 0, acc11 = 0;

    #pragma unroll 1
    for (int kt = 0; kt < 16; ++kt) {
        const int buf = kt & 1;
        if (kt < 15) {
            ra = *(const float4*)(Ag + (kt + 1) * 32);
            rb = *(const float2*)(Bg + (size_t)(kt + 1) * 32 * HH);
        }

        const float* ap = &sA[buf][kbase * 64 + mloc];
        const float* bp = &sBd[buf][kbase * 64 + nloc * 2];
        #pragma unroll
        for (int k = 0; k < 16; ++k) {
            ulonglong2 av = *(const ulonglong2*)(ap + k * 64);
            ulonglong2 bv = *(const ulonglong2*)(bp + k * 64);
            acc00 = fma2(av.x, bv.x, acc00);
            acc01 = fma2(av.x, bv.y, acc01);
            acc10 = fma2(av.y, bv.x, acc10);
            acc11 = fma2(av.y, bv.y, acc11);
        }

        if (kt < 15) {
            float* dA = sA[buf ^ 1];
            float* dB = sBd[buf ^ 1];
            dA[(ak4 + 0) * 64 + am] = ra.x;
            dA[(ak4 + 1) * 64 + am] = ra.y;
            dA[(ak4 + 2) * 64 + am] = ra.z;
            dA[(ak4 + 3) * 64 + am] = ra.w;
            *(float4*)&dB[bk * 64 + bnp * 4] = make_float4(rb.x, rb.x, rb.y, rb.y);
            __syncthreads();
        }
    }

    // ---- K-split reduction via smem (reuse sA[0] = 8 KB) ----
    ull* sRed = (ull*)&sA[0][0];        // 256 slots x 4 ull
    const int slot = (wg * 32 + lane) * 4;
    if (kg == 1) {
        *(ulonglong2*)&sRed[slot + 0] = make_ulonglong2(acc00, acc01);
        *(ulonglong2*)&sRed[slot + 2] = make_ulonglong2(acc10, acc11);
    }
    __syncthreads();
    if (kg == 1) return;   // no more syncs below

    {
        ulonglong2 pa = *(const ulonglong2*)&sRed[slot + 0];
        ulonglong2 pb = *(const ulonglong2*)&sRed[slot + 2];
        float2 a, b;
        a = unpack2(acc00); b = unpack2(pa.x); acc00 = pack2(a.x + b.x, a.y + b.y);
        a = unpack2(acc01); b = unpack2(pa.y); acc01 = pack2(a.x + b.x, a.y + b.y);
        a = unpack2(acc10); b = unpack2(pb.x); acc10 = pack2(a.x + b.x, a.y + b.y);
        a = unpack2(acc11); b = unpack2(pb.y); acc11 = pack2(a.x + b.x, a.y + b.y);
    }

    // ---- fused gate epilogue (256 threads, 4 rows x 2 cols each) ----
    const int r0  = m0 + mloc;
    const int col = n0 + nloc;
    const float* xwt = g_xw + (size_t)t * (BB * HH);

    const float* gp = g_gp + (size_t)(col >> 1) * 20;
    float4 p0 = *(const float4*)(gp + 0);
    float4 p1 = *(const float4*)(gp + 4);
    float4 p2 = *(const float4*)(gp + 8);
    float4 p3 = *(const float4*)(gp + 12);
    float4 p4 = *(const float4*)(gp + 16);

    float cc[2][3]  = {{p0.x, p0.y, p0.z}, {p2.z, p2.w, p3.x}};
    float bb2[2]    = {p0.w, p3.y};
    float iv[2][3]  = {{p1.x, p1.y, p1.z}, {p3.z, p3.w, p4.x}};
    float qq[2][3]  = {{p1.w, p2.x, p2.y}, {p4.y, p4.z, p4.w}};

    float zr[4][2];
    { float2 v = unpack2(acc00); zr[0][0] = v.x; zr[1][0] = v.y; }
    { float2 v = unpack2(acc01); zr[0][1] = v.x; zr[1][1] = v.y; }
    { float2 v = unpack2(acc10); zr[2][0] = v.x; zr[3][0] = v.y; }
    { float2 v = unpack2(acc11); zr[2][1] = v.x; zr[3][1] = v.y; }

    #pragma unroll
    for (int i = 0; i < 4; ++i) {
        const size_t off = (size_t)(r0 + i) * HH + col;
        float2 xv = *(const float2*)&xwt[off];
        float2 hv = *(const float2*)&hcur[off];
        float hn[2];
        #pragma unroll
        for (int j = 0; j < 2; ++j) {
            float x  = j ? xv.y : xv.x;
            float hi = j ? hv.y : hv.x;
            float z  = zr[i][j] + x + bb2[j];
            float d0 = z - cc[j][0], d1 = z - cc[j][1], d2 = z - cc[j][2];
            float mu0 = __expf(-d0 * d0 * iv[j][0]);
            float mu1 = __expf(-d1 * d1 * iv[j][1]);
            float mu2 = __expf(-d2 * d2 * iv[j][2]);
            float num = mu0 * qq[j][0] + mu1 * qq[j][1] + mu2 * qq[j][2];
            float den = mu0 + mu1 + mu2 + 1e-8f;
            float g   = 1.0f / (1.0f + __expf(-num / den));
            float ex  = __expf(-2.0f * x);
            float ni  = (1.0f - ex) / (1.0f + ex);
            hn[j] = (1.0f - g) * hi + g * ni;
        }
        *(float2*)&hnxt[off] = make_float2(hn[0], hn[1]);
    }
}

// ------------------------------------------------------------------
// Final: logits[b] = h_final[b] . Wc + bc ; one warp per batch row.
// ------------------------------------------------------------------
__global__ void __launch_bounds__(256) final_kernel(const float* __restrict__ Wc,
                                                    const float* __restrict__ bc,
                                                    float* __restrict__ out)
{
    const int warp = threadIdx.x >> 5;
    const int lane = threadIdx.x & 31;
    const int b = blockIdx.x * 8 + warp;       // 64 blocks x 8 warps = 512
    const float* hrow = g_h2[0] + (size_t)b * HH;
    float s = 0.0f;
    #pragma unroll
    for (int i = 0; i < 4; ++i) {
        float4 h4 = *(const float4*)&hrow[i * 128 + lane * 4];
        float4 w4 = *(const float4*)&Wc[i * 128 + lane * 4];
        s += h4.x * w4.x + h4.y * w4.y + h4.z * w4.z + h4.w * w4.w;
    }
    #pragma unroll
    for (int o = 16; o > 0; o >>= 1) s += __shfl_down_sync(0xffffffffu, s, o);
    if (lane == 0) out[b] = s + bc[0];
}

// ------------------------------------------------------------------
// Launch
// ------------------------------------------------------------------
extern "C" void kernel_launch(void* const* d_in, const int* in_sizes, int n_in,
                              void* d_out, int out_size)
{
    const float* x     = (const float*)d_in[0];
    const float* theta = (const float*)d_in[1];
    const float* Wx    = (const float*)d_in[2];
    const float* Wh    = (const float*)d_in[3];
    const float* bias  = (const float*)d_in[4];
    const float* c     = (const float*)d_in[5];
    const float* sigma = (const float*)d_in[6];
    const float* q     = (const float*)d_in[7];
    const float* Wc    = (const float*)d_in[8];
    const float* bc    = (const float*)d_in[9];
    float* out = (float*)d_out;

    prep_kernel<<<(BB * HH + 255) / 256, 256>>>(theta, Wx, sigma, c, q, bias, out);
    gemm1_kernel<<<dim3((BB * TT) / 128, HH / 128), 256>>>(x);
    for (int t = 0; t < TT; ++t)
        step_kernel<<<dim3(8, 16), 512>>>(Wh, t);
    final_kernel<<<64, 256>>>(Wc, bc, out);
}

// round 5
// speedup vs baseline: 1.3202x; 1.2579x over previous
#include <cuda_runtime.h>
#include <cuda_bf16.h>
#include <math.h>

#define BB   512   // batch
#define TT   128   // time steps
#define FF   256   // features
#define HH   512   // hidden
#define KK   3     // fuzzy rules

typedef unsigned long long ull;

// ------------------------------------------------------------------
// Device scratch
// ------------------------------------------------------------------
__device__ float g_xw[(size_t)TT * BB * HH];   // [T][B][H]
__device__ float g_h2[2][(size_t)BB * HH];     // ping-pong hidden state [B][H]
__device__ float g_Wxs[FF * HH];               // diag(sigmoid(theta)) @ Wx
__device__ float g_gp[(HH / 2) * 20];          // packed gate params per column-pair

// ------------------------------------------------------------------
// Packed f32x2 helpers
// ------------------------------------------------------------------
__device__ __forceinline__ ull pack2(float x, float y) {
    ull r; asm("mov.b64 %0, {%1, %2};" : "=l"(r) : "f"(x), "f"(y)); return r;
}
__device__ __forceinline__ float2 unpack2(ull v) {
    float2 r; asm("mov.b64 {%0, %1}, %2;" : "=f"(r.x), "=f"(r.y) : "l"(v)); return r;
}
__device__ __forceinline__ ull fma2(ull a, ull b, ull c) {
    ull d; asm("fma.rn.f32x2 %0, %1, %2, %3;" : "=l"(d) : "l"(a), "l"(b), "l"(c)); return d;
}

// ------------------------------------------------------------------
// Prep: zero h0, fold selector into Wx, emit weights, pack gate params.
// gp layout per column-pair (cols 2p, 2p+1), 20 floats:
//  [0..2]=c0 [3]=b0 [4..6]=inv0 [7..9]=q0 ; [10..12]=c1 [13]=b1 [14..16]=inv1 [17..19]=q1
// ------------------------------------------------------------------
__global__ void prep_kernel(const float* __restrict__ theta,
                            const float* __restrict__ Wx,
                            const float* __restrict__ sigma,
                            const float* __restrict__ cC,
                            const float* __restrict__ qQ,
                            const float* __restrict__ bias,
                            float* __restrict__ out)
{
    int idx = blockIdx.x * blockDim.x + threadIdx.x;
    if (idx < BB * HH) g_h2[0][idx] = 0.0f;
    if (idx < FF * HH) {
        int f = idx >> 9;
        float w = 1.0f / (1.0f + expf(-theta[f]));
        g_Wxs[idx] = w * Wx[idx];
    }
    if (idx < FF) out[BB + idx] = 1.0f / (1.0f + expf(-theta[idx]));
    if (idx < HH / 2) {
        float* gp = g_gp + idx * 20;
        #pragma unroll
        for (int j = 0; j < 2; ++j) {
            int col = idx * 2 + j;
            float* o = gp + j * 10;
            #pragma unroll
            for (int s = 0; s < 3; ++s) {
                float sg = sigma[col * 3 + s];
                o[0 + s] = cC[col * 3 + s];
                o[4 + s] = 1.0f / (2.0f * sg * sg + 1e-8f);
                o[7 + s] = qQ[col * 3 + s];
            }
            o[3] = bias[col];
        }
    }
}

// ------------------------------------------------------------------
// GEMM1 (proven): g_xw[t][b][h] = sum_f x[b][t][f] * Wxs[f][h]
// ------------------------------------------------------------------
__global__ void __launch_bounds__(256) gemm1_kernel(const float* __restrict__ x)
{
    __shared__ float sA[16][130];
    __shared__ float sB[16][128];

    const int tid = threadIdx.x;
    const int m0  = blockIdx.x * 128;
    const int n0  = blockIdx.y * 128;

    const int ar = tid >> 1;
    const int ak = (tid & 1) * 8;
    const int bk = tid >> 4;
    const int bc = (tid & 15) * 8;

    const float* Ag = x     + (size_t)(m0 + ar) * FF + ak;
    const float* Bg = g_Wxs + (size_t)bk * HH + n0 + bc;

    float4 ra0 = *(const float4*)(Ag);
    float4 ra1 = *(const float4*)(Ag + 4);
    float4 rb0 = *(const float4*)(Bg);
    float4 rb1 = *(const float4*)(Bg + 4);

    ull acc[4][8];
    #pragma unroll
    for (int i = 0; i < 4; ++i)
        #pragma unroll
        for (int j = 0; j < 8; ++j) acc[i][j] = 0ull;

    const int ty = tid >> 4;
    const int tx = tid & 15;

    #pragma unroll 1
    for (int kt = 0; kt < FF / 16; ++kt) {
        sA[ak + 0][ar] = ra0.x; sA[ak + 1][ar] = ra0.y;
        sA[ak + 2][ar] = ra0.z; sA[ak + 3][ar] = ra0.w;
        sA[ak + 4][ar] = ra1.x; sA[ak + 5][ar] = ra1.y;
        sA[ak + 6][ar] = ra1.z; sA[ak + 7][ar] = ra1.w;
        *(float4*)&sB[bk][bc]     = rb0;
        *(float4*)&sB[bk][bc + 4] = rb1;
        __syncthreads();

        if (kt < FF / 16 - 1) {
            const float* Ag2 = Ag + (kt + 1) * 16;
            const float* Bg2 = Bg + (size_t)(kt + 1) * 16 * HH;
            ra0 = *(const float4*)(Ag2);
            ra1 = *(const float4*)(Ag2 + 4);
            rb0 = *(const float4*)(Bg2);
            rb1 = *(const float4*)(Bg2 + 4);
        }

        #pragma unroll
        for (int kk = 0; kk < 16; ++kk) {
            ull a2[4];
            #pragma unroll
            for (int i = 0; i < 4; ++i)
                a2[i] = *(const ull*)&sA[kk][ty * 8 + 2 * i];
            float bf[8];
            *(float4*)&bf[0] = *(const float4*)&sB[kk][tx * 8];
            *(float4*)&bf[4] = *(const float4*)&sB[kk][tx * 8 + 4];
            #pragma unroll
            for (int j = 0; j < 8; ++j) {
                ull bbv = pack2(bf[j], bf[j]);
                #pragma unroll
                for (int i = 0; i < 4; ++i)
                    acc[i][j] = fma2(a2[i], bbv, acc[i][j]);
            }
        }
        __syncthreads();
    }

    #pragma unroll
    for (int i = 0; i < 4; ++i) {
        float2 v[8];
        #pragma unroll
        for (int j = 0; j < 8; ++j) v[j] = unpack2(acc[i][j]);
        #pragma unroll
        for (int p = 0; p < 2; ++p) {
            int m = m0 + ty * 8 + 2 * i + p;
            int t = m & (TT - 1);
            int b = m >> 7;
            float* orow = g_xw + ((size_t)t * BB + b) * HH + n0 + tx * 8;
            float4 o0, o1;
            if (p == 0) {
                o0 = make_float4(v[0].x, v[1].x, v[2].x, v[3].x);
                o1 = make_float4(v[4].x, v[5].x, v[6].x, v[7].x);
            } else {
                o0 = make_float4(v[0].y, v[1].y, v[2].y, v[3].y);
                o1 = make_float4(v[4].y, v[5].y, v[6].y, v[7].y);
            }
            *(float4*)(orow)     = o0;
            *(float4*)(orow + 4) = o1;
        }
    }
}

// ------------------------------------------------------------------
// Step kernel v5: 256 threads, K-split x2, 4m x 4n thread tiles.
// CTA tile 32(batch) x 64(hidden), grid 16x8 = 128 CTAs.
// BK=32, double-buffered smem; warps 0-3 do k[0:16) of each chunk,
// warps 4-7 do k[16:32). 32 MACs per 8 LDS phases (2x fewer crossbar
// phases per MAC than before).
// ------------------------------------------------------------------
__global__ void __launch_bounds__(256, 1) step_kernel(const float* __restrict__ Wh,
                                                      int t)
{
    __shared__ float sA[2][32 * 32];    // [buf][k][m]  2 x 4 KB
    __shared__ float sB[2][32 * 64];    // [buf][k][n]  2 x 8 KB

    const int tid = threadIdx.x;
    const int m0  = blockIdx.x * 32;    // grid.x = 16
    const int n0  = blockIdx.y * 64;    // grid.y = 8

    const float* hcur = g_h2[t & 1];
    float*       hnxt = g_h2[(t + 1) & 1];

    const int warp = tid >> 5;
    const int lane = tid & 31;
    const int kg   = warp >> 2;          // k-split group 0/1
    const int wg   = warp & 3;           // warp-in-group
    // warp tile 16m x 32n ; thread tile 4m x 4n
    const int mloc = (wg & 1) * 16 + (lane & 3) * 4;
    const int nloc = (wg >> 1) * 32 + (lane >> 2) * 4;
    const int kbase = kg * 16;

    // staging indices (256 threads)
    const int am  = tid & 31;            // batch row 0..31
    const int ak4 = (tid >> 5) << 2;     // k quad base 0,4,...,28
    const int bk  = tid >> 3;            // k row 0..31
    const int bn8 = (tid & 7) * 8;       // n offset 0..56

    const float* Ag = hcur + (size_t)(m0 + am) * HH + ak4;
    const float* Bg = Wh   + (size_t)bk * HH + n0 + bn8;

    // ---- prologue: stage chunk 0 ----
    float4 ra  = *(const float4*)(Ag);
    float4 rb0 = *(const float4*)(Bg);
    float4 rb1 = *(const float4*)(Bg + 4);
    sA[0][(ak4 + 0) * 32 + am] = ra.x;
    sA[0][(ak4 + 1) * 32 + am] = ra.y;
    sA[0][(ak4 + 2) * 32 + am] = ra.z;
    sA[0][(ak4 + 3) * 32 + am] = ra.w;
    *(float4*)&sB[0][bk * 64 + bn8]     = rb0;
    *(float4*)&sB[0][bk * 64 + bn8 + 4] = rb1;
    __syncthreads();

    ull acc[2][4];
    #pragma unroll
    for (int i = 0; i < 2; ++i)
        #pragma unroll
        for (int j = 0; j < 4; ++j) acc[i][j] = 0ull;

    #pragma unroll 1
    for (int kt = 0; kt < 16; ++kt) {
        const int buf = kt & 1;
        if (kt < 15) {
            ra  = *(const float4*)(Ag + (kt + 1) * 32);
            rb0 = *(const float4*)(Bg + (size_t)(kt + 1) * 32 * HH);
            rb1 = *(const float4*)(Bg + (size_t)(kt + 1) * 32 * HH + 4);
        }

        const float* ap = &sA[buf][kbase * 32 + mloc];
        const float* bp = &sB[buf][kbase * 64 + nloc];
        #pragma unroll
        for (int k = 0; k < 16; ++k) {
            ulonglong2 av = *(const ulonglong2*)(ap + k * 32);   // 4 m floats
            float4     bv = *(const float4*)(bp + k * 64);       // 4 n floats
            ull b0 = pack2(bv.x, bv.x);
            ull b1 = pack2(bv.y, bv.y);
            ull b2 = pack2(bv.z, bv.z);
            ull b3 = pack2(bv.w, bv.w);
            acc[0][0] = fma2(av.x, b0, acc[0][0]);
            acc[0][1] = fma2(av.x, b1, acc[0][1]);
            acc[0][2] = fma2(av.x, b2, acc[0][2]);
            acc[0][3] = fma2(av.x, b3, acc[0][3]);
            acc[1][0] = fma2(av.y, b0, acc[1][0]);
            acc[1][1] = fma2(av.y, b1, acc[1][1]);
            acc[1][2] = fma2(av.y, b2, acc[1][2]);
            acc[1][3] = fma2(av.y, b3, acc[1][3]);
        }

        if (kt < 15) {
            float* dA = sA[buf ^ 1];
            float* dB = sB[buf ^ 1];
            dA[(ak4 + 0) * 32 + am] = ra.x;
            dA[(ak4 + 1) * 32 + am] = ra.y;
            dA[(ak4 + 2) * 32 + am] = ra.z;
            dA[(ak4 + 3) * 32 + am] = ra.w;
            *(float4*)&dB[bk * 64 + bn8]     = rb0;
            *(float4*)&dB[bk * 64 + bn8 + 4] = rb1;
            __syncthreads();
        }
    }

    // ---- K-split reduction via smem (reuse sA = 8 KB) ----
    ull* sRed = (ull*)&sA[0][0];          // 128 slots x 8 ull = 8 KB
    const int slot = (wg * 32 + lane) * 8;
    if (kg == 1) {
        *(ulonglong2*)&sRed[slot + 0] = make_ulonglong2(acc[0][0], acc[0][1]);
        *(ulonglong2*)&sRed[slot + 2] = make_ulonglong2(acc[0][2], acc[0][3]);
        *(ulonglong2*)&sRed[slot + 4] = make_ulonglong2(acc[1][0], acc[1][1]);
        *(ulonglong2*)&sRed[slot + 6] = make_ulonglong2(acc[1][2], acc[1][3]);
    }
    __syncthreads();
    if (kg == 1) return;

    #pragma unroll
    for (int i = 0; i < 2; ++i)
        #pragma unroll
        for (int j = 0; j < 4; ++j) {
            float2 a = unpack2(acc[i][j]);
            float2 b = unpack2(sRed[slot + i * 4 + j]);
            acc[i][j] = pack2(a.x + b.x, a.y + b.y);
        }

    // ---- fused gate epilogue: 4 rows x 4 cols per thread ----
    const int r0  = m0 + mloc;
    const int col = n0 + nloc;                 // multiple of 4
    const float* xwt = g_xw + (size_t)t * (BB * HH);

    // z values: zr[row 0..3][col 0..3]
    float zr[4][4];
    #pragma unroll
    for (int i = 0; i < 2; ++i)
        #pragma unroll
        for (int j = 0; j < 4; ++j) {
            float2 v = unpack2(acc[i][j]);
            zr[i * 2 + 0][j] = v.x;
            zr[i * 2 + 1][j] = v.y;
        }

    // gate params for 2 column-pairs
    float cc[4][3], iv[4][3], qq[4][3], bb2[4];
    #pragma unroll
    for (int jp = 0; jp < 2; ++jp) {
        const float* gp = g_gp + (size_t)((col >> 1) + jp) * 20;
        float4 p0 = *(const float4*)(gp + 0);
        float4 p1 = *(const float4*)(gp + 4);
        float4 p2 = *(const float4*)(gp + 8);
        float4 p3 = *(const float4*)(gp + 12);
        float4 p4 = *(const float4*)(gp + 16);
        int j0 = jp * 2, j1 = jp * 2 + 1;
        cc[j0][0] = p0.x; cc[j0][1] = p0.y; cc[j0][2] = p0.z; bb2[j0] = p0.w;
        iv[j0][0] = p1.x; iv[j0][1] = p1.y; iv[j0][2] = p1.z;
        qq[j0][0] = p1.w; qq[j0][1] = p2.x; qq[j0][2] = p2.y;
        cc[j1][0] = p2.z; cc[j1][1] = p2.w; cc[j1][2] = p3.x; bb2[j1] = p3.y;
        iv[j1][0] = p3.z; iv[j1][1] = p3.w; iv[j1][2] = p4.x;
        qq[j1][0] = p4.y; qq[j1][1] = p4.z; qq[j1][2] = p4.w;
    }

    #pragma unroll
    for (int i = 0; i < 4; ++i) {
        const size_t off = (size_t)(r0 + i) * HH + col;
        float4 xv = *(const float4*)&xwt[off];
        float4 hv = *(const float4*)&hcur[off];
        float xa[4] = {xv.x, xv.y, xv.z, xv.w};
        float ha[4] = {hv.x, hv.y, hv.z, hv.w};
        float hn[4];
        #pragma unroll
        for (int j = 0; j < 4; ++j) {
            float x  = xa[j];
            float z  = zr[i][j] + x + bb2[j];
            float d0 = z - cc[j][0], d1 = z - cc[j][1], d2 = z - cc[j][2];
            float mu0 = __expf(-d0 * d0 * iv[j][0]);
            float mu1 = __expf(-d1 * d1 * iv[j][1]);
            float mu2 = __expf(-d2 * d2 * iv[j][2]);
            float num = mu0 * qq[j][0] + mu1 * qq[j][1] + mu2 * qq[j][2];
            float den = mu0 + mu1 + mu2 + 1e-8f;
            float g   = 1.0f / (1.0f + __expf(-num / den));
            float ex  = __expf(-2.0f * x);
            float ni  = (1.0f - ex) / (1.0f + ex);
            hn[j] = (1.0f - g) * ha[j] + g * ni;
        }
        *(float4*)&hnxt[off] = make_float4(hn[0], hn[1], hn[2], hn[3]);
    }
}

// ------------------------------------------------------------------
// Final: logits[b] = h_final[b] . Wc + bc ; one warp per batch row.
// ------------------------------------------------------------------
__global__ void __launch_bounds__(256) final_kernel(const float* __restrict__ Wc,
                                                    const float* __restrict__ bc,
                                                    float* __restrict__ out)
{
    const int warp = threadIdx.x >> 5;
    const int lane = threadIdx.x & 31;
    const int b = blockIdx.x * 8 + warp;       // 64 blocks x 8 warps = 512
    const float* hrow = g_h2[0] + (size_t)b * HH;
    float s = 0.0f;
    #pragma unroll
    for (int i = 0; i < 4; ++i) {
        float4 h4 = *(const float4*)&hrow[i * 128 + lane * 4];
        float4 w4 = *(const float4*)&Wc[i * 128 + lane * 4];
        s += h4.x * w4.x + h4.y * w4.y + h4.z * w4.z + h4.w * w4.w;
    }
    #pragma unroll
    for (int o = 16; o > 0; o >>= 1) s += __shfl_down_sync(0xffffffffu, s, o);
    if (lane == 0) out[b] = s + bc[0];
}

// ------------------------------------------------------------------
// Launch
// ------------------------------------------------------------------
extern "C" void kernel_launch(void* const* d_in, const int* in_sizes, int n_in,
                              void* d_out, int out_size)
{
    const float* x     = (const float*)d_in[0];
    const float* theta = (const float*)d_in[1];
    const float* Wx    = (const float*)d_in[2];
    const float* Wh    = (const float*)d_in[3];
    const float* bias  = (const float*)d_in[4];
    const float* c     = (const float*)d_in[5];
    const float* sigma = (const float*)d_in[6];
    const float* q     = (const float*)d_in[7];
    const float* Wc    = (const float*)d_in[8];
    const float* bc    = (const float*)d_in[9];
    float* out = (float*)d_out;

    prep_kernel<<<(BB * HH + 255) / 256, 256>>>(theta, Wx, sigma, c, q, bias, out);
    gemm1_kernel<<<dim3((BB * TT) / 128, HH / 128), 256>>>(x);
    for (int t = 0; t < TT; ++t)
        step_kernel<<<dim3(16, 8), 256>>>(Wh, t);
    final_kernel<<<64, 256>>>(Wc, bc, out);
}